// round 8
// baseline (speedup 1.0000x reference)
#include <cuda_runtime.h>

#define N0 16
#define N1 200
#define N2 200
#define NPIX (N1*N2)          // 40000
#define NVOX (N0*NPIX)        // 640000
#define NPHI 190
#define NRAD 223
#define NT 351
#define GR 4                  // gaussian radius
#define NSLOT (NPHI*NRAD)     // 42370
#define NCH 8                 // phi chunks for backprojection
#define CHW 24                // ceil(190/8)
#define NPAIR (NPIX/2)        // 20000 pixel pairs

// ---------------- scratch (device globals; no allocation allowed) ----------
__device__ __align__(16) float d_GW[2*GR+1];
__device__ float d_COS[NPHI];
__device__ float d_SIN[NPHI];
__device__ float d_RV[NRAD];
__device__ __align__(16) float d_buf0[NVOX];
__device__ __align__(16) float d_buf1[NVOX];
__device__ __align__(16) float d_st2[2*NVOX + 2*N0*N2];  // paired img + pad i-row
__device__ __align__(16) float d_zr[NSLOT*N0];           // mult*data/exp, [sidx][z]
__device__ __align__(16) float d_bp[NCH*NVOX];           // backprojection partials

// ---------------- packed f32x2 helpers (Blackwell) --------------------------
__device__ __forceinline__ unsigned long long f2_pack(float a, float b)
{
    unsigned long long r;
    asm("mov.b64 %0, {%1,%2};" : "=l"(r) : "f"(a), "f"(b));
    return r;
}
__device__ __forceinline__ void f2_fma(unsigned long long& d,
                                       unsigned long long a, unsigned long long b)
{
    asm("fma.rn.f32x2 %0, %1, %2, %0;" : "+l"(d) : "l"(a), "l"(b));
}
__device__ __forceinline__ unsigned long long f2_add(unsigned long long a,
                                                     unsigned long long b)
{
    unsigned long long r;
    asm("add.rn.f32x2 %0, %1, %2;" : "=l"(r) : "l"(a), "l"(b));
    return r;
}
__device__ __forceinline__ float2 f2_unpack(unsigned long long v)
{
    float2 r;
    asm("mov.b64 {%0,%1}, %2;" : "=f"(r.x), "=f"(r.y) : "l"(v));
    return r;
}

// ---------------- constant tables (match numpy float64 -> float32) ---------
__global__ void k_init()
{
    int t = blockIdx.x * blockDim.x + threadIdx.x;
    if (t == 0) {
        const double sigma = 4.5 / (2.35 * 2.0);
        double g[2*GR+1];
        double sum = 0.0;
        for (int k = 0; k <= 2*GR; k++) {
            double d = (double)(k - GR) / sigma;
            g[k] = exp(-0.5 * d * d);
            sum += g[k];
        }
        for (int k = 0; k <= 2*GR; k++) d_GW[k] = (float)(g[k] / sum);
    }
    const double PI = 3.14159265358979323846;
    for (int i = t; i < NPHI; i += blockDim.x * gridDim.x) {
        float phi = (float)((double)i * (PI / 190.0));   // linspace f64 -> f32
        d_COS[i] = (float)cos((double)phi);
        d_SIN[i] = (float)sin((double)phi);
    }
    for (int i = t; i < NRAD; i += blockDim.x * gridDim.x) {
        d_RV[i] = (float)(-200.0 + (double)i * (400.0 / 222.0));
    }
}

__device__ __forceinline__ int refl(int m, int n)
{
    if (m < 0)  m = -1 - m;
    if (m >= n) m = 2*n - 1 - m;
    return m;
}

// ---------------- fused forward gauss3 + paired z-transpose -----------------
__global__ void k_gauss3t2(const float* __restrict__ in, float* __restrict__ out2)
{
    __shared__ float ta[N0][N2 + 1];
    __shared__ float tb[N0][N2 + 1];
    int i = blockIdx.x;
    int ridx[2*GR+1];
    #pragma unroll
    for (int d = -GR; d <= GR; d++) ridx[d+GR] = refl(i + d, N1);
    // phase 1: i-smooth
    for (int t = threadIdx.x; t < N0*N2; t += blockDim.x) {
        int j = t % N2;
        int z = t / N2;
        const float* base = in + z*NPIX + j;
        float s = 0.f;
        #pragma unroll
        for (int d = 0; d < 2*GR+1; d++)
            s += d_GW[d] * base[ridx[d]*N2];
        ta[z][j] = s;
    }
    __syncthreads();
    // phase 2: j-smooth (ta -> tb)
    for (int t = threadIdx.x; t < N0*N2; t += blockDim.x) {
        int j = t % N2;
        int z = t / N2;
        float s = 0.f;
        if (j >= GR && j < N2-GR) {
            #pragma unroll
            for (int d = -GR; d <= GR; d++)
                s += d_GW[d+GR] * ta[z][j+d];
        } else {
            #pragma unroll
            for (int d = -GR; d <= GR; d++)
                s += d_GW[d+GR] * ta[z][refl(j+d, N2)];
        }
        tb[z][j] = s;
    }
    __syncthreads();
    // phase 3: z-smooth (tb -> ta)
    for (int t = threadIdx.x; t < N0*N2; t += blockDim.x) {
        int j = t % N2;
        int z = t / N2;
        float s = 0.f;
        #pragma unroll
        for (int d = -GR; d <= GR; d++) {
            int m = z + d;
            if (m < 0)   m = -1 - m;
            if (m >= N0) m = 2*N0 - 1 - m;
            s += d_GW[d+GR] * tb[m][j];
        }
        ta[z][j] = s;
    }
    __syncthreads();
    // phase 4: paired-z writes
    for (int t = threadIdx.x; t < N0*N2; t += blockDim.x) {
        int z = t & (N0-1);
        int j = t >> 4;
        int j1 = min(j + 1, N2 - 1);
        float v0 = ta[z][j];
        float v1 = ta[z][j1];
        unsigned base = ((unsigned)(i*N2 + j)) << 5;
        out2[base + z]      = v0;
        out2[base + N0 + z] = v1;
        if (i == N1-1) {   // pad row i = N1 duplicates i = N1-1
            unsigned pbase = ((unsigned)(N1*N2 + j)) << 5;
            out2[pbase + z]      = v0;
            out2[pbase + N0 + z] = v1;
        }
    }
}

// ---------------- forward projection + ratio (fused) ------------------------
// 8 lanes per ray, same sample n; lanes load one 128B pair-block per corner in
// a single warp-LDG. ulonglong2 loads feed fma.rn.f32x2 directly (no packs).
__global__ void k_project(const float* __restrict__ st2,
                          const float* __restrict__ data,
                          const float* __restrict__ contam,
                          const float* __restrict__ mult,
                          float* __restrict__ zr)
{
    int t = blockIdx.x * blockDim.x + threadIdx.x;
    int lane8 = t & 7;
    int ray   = t >> 3;
    bool live = (ray < NSLOT);
    if (!live) ray = NSLOT - 1;           // clamp: keep all 32 lanes for shfl
    int phi = ray / NRAD;
    int rad = ray - phi * NRAD;
    int zq  = lane8 & 3;
    bool isj1 = lane8 >= 4;
    float wjb = isj1 ? 0.f : 1.f;         // wj = fma(fj, wjs, wjb)
    float wjs = isj1 ? 1.f : -1.f;

    float c = d_COS[phi], s = d_SIN[phi];
    float r = d_RV[rad];
    float rns = r * (-s);
    float rc  = r * c;

    float A = 0.5f * (rns + 199.f) - 175.f * c;
    float B = 0.5f * (rc  + 199.f) - 175.f * s;

    const float EPS = 1e-6f;
    float lo = 0.f, hi = 350.f;
    bool empty = false;
    if (fabsf(c) > EPS) {
        float n0 = (0.f   - A) / c;
        float n1 = (199.f - A) / c;
        lo = fmaxf(lo, fminf(n0, n1)); hi = fminf(hi, fmaxf(n0, n1));
    } else if (A < 0.f || A > 199.f) empty = true;
    if (fabsf(s) > EPS) {
        float n0 = (0.f   - B) / s;
        float n1 = (199.f - B) / s;
        lo = fmaxf(lo, fminf(n0, n1)); hi = fminf(hi, fmaxf(n0, n1));
    } else if (B < 0.f || B > 199.f) empty = true;

    unsigned long long acc01 = 0ull, acc23 = 0ull;
    if (!empty && hi >= lo) {
        int nlo = max(0,    (int)floorf(lo) - 1);
        int nhi = min(NT-1, (int)ceilf (hi) + 1);
        float hc = 0.5f * c, hs = 0.5f * s;
        float Kx = 0.5f * (rns + 199.f);
        float Ky = 0.5f * (rc  + 199.f);
        float tn = -350.f + 2.f * (float)nlo;
        for (int n = nlo; n <= nhi; n++, tn += 2.f) {
            float ix = __fmaf_rn(tn, hc, Kx);
            float iy = __fmaf_rn(tn, hs, Ky);
            if (ix < 0.f || ix > 199.f || iy < 0.f || iy > 199.f) continue;
            int i0 = (int)ix;
            int j0 = (int)iy;
            float fi = ix - (float)i0;
            float fj = iy - (float)j0;
            float wj = __fmaf_rn(fj, wjs, wjb);
            unsigned base = ((unsigned)(i0*N2 + j0)) << 5;
            const unsigned iofs = (unsigned)(N2*2*N0);            // pad row
            ulonglong2 q0 = *((const ulonglong2*)(st2 + base) + lane8);
            ulonglong2 q1 = *((const ulonglong2*)(st2 + base + iofs) + lane8);
            float w0 = wj * (1.f - fi);
            float w1 = wj * fi;
            unsigned long long w0p = f2_pack(w0, w0);
            unsigned long long w1p = f2_pack(w1, w1);
            f2_fma(acc01, w0p, q0.x);
            f2_fma(acc01, w1p, q1.x);
            f2_fma(acc23, w0p, q0.y);
            f2_fma(acc23, w1p, q1.y);
        }
    }

    acc01 = f2_add(acc01, __shfl_down_sync(0xffffffffu, acc01, 4));
    acc23 = f2_add(acc23, __shfl_down_sync(0xffffffffu, acc23, 4));

    if (live && !isj1) {
        int sidx = ray;
        float2 u01 = f2_unpack(acc01);
        float2 u23 = f2_unpack(acc23);
        float pr[4] = { u01.x*2.f, u01.y*2.f, u23.x*2.f, u23.y*2.f };
        float4 o;
        float* ov = (float*)&o;
        #pragma unroll
        for (int k = 0; k < 4; k++) {
            int gi = (zq*4 + k) * NSLOT + sidx;
            float mm = mult[gi];
            float e  = __fmaf_rn(mm, pr[k], contam[gi]);
            ov[k] = mm * data[gi] / e;
        }
        ((float4*)zr)[sidx*4 + zq] = o;
    }
}

// ---------------- backprojection (exact adjoint, pixel-pair gather) ---------
// one thread = (pixel pair (i, j0=2jj, j0+1), phi-chunk). dx is shared between
// the two pixels; sample validity is pixel-independent. One zr row load feeds
// both pixels' packed accumulators.
__global__ void k_backproject(const float* __restrict__ zr, float* __restrict__ bp)
{
    int tid = blockIdx.x * blockDim.x + threadIdx.x;
    if (tid >= NCH * NPAIR) return;
    int pair = tid % NPAIR;
    int ch   = tid / NPAIR;
    int i  = pair / (N2/2);
    int jj = pair - i * (N2/2);
    int j0 = jj * 2;
    float X  = -199.f + 2.f * (float)i;
    float Ym = -199.f + 2.f * (float)j0 + 1.f;   // pair midpoint

    unsigned long long a0[8], a1[8];
    #pragma unroll
    for (int k = 0; k < 8; k++) { a0[k] = 0ull; a1[k] = 0ull; }

    const float inv_dr = (float)(222.0 / 400.0);
    float cx  = 99.5f - (float)i;     // dx(tn) = tn*hc + fma(rm,-hs,cx)
    float cy0 = 99.5f - (float)j0;    // dy0(tn) = tn*hs + fma(rm,hc,cy0); dy1 = dy0-1
    // validity windows (sample-global): ix in [0,199] <=> dx in [vxl,vxh]; same for iy
    float vxl = -(float)i,  vxh = 199.f - (float)i;
    float vyl = -(float)j0, vyh = 199.f - (float)j0;
    bool interior = (i >= 1 && i <= N1-2) && (jj >= 1 && jj <= N2/2 - 2);

    int plo = ch * CHW;
    int phi_end = min(NPHI, plo + CHW);

    for (int phi = plo; phi < phi_end; phi++) {
        float c = d_COS[phi], s = d_SIN[phi];
        float ac = fabsf(c), as = fabsf(s);
        float lim  = 2.f * (ac + as) + 1e-2f;
        float limR = lim + ac;               // union over the 2 pixels (+-c in r)
        float limT = lim + as;               // (+-s in t)
        float r0 = -X*s + Ym*c;
        float t0 =  X*c + Ym*s;
        int mlo = max(0,      (int)ceilf ((r0 + 200.f - limR) * inv_dr));
        int mhi = min(NRAD-1, (int)floorf((r0 + 200.f + limR) * inv_dr));
        int nlo = max(0,      (int)ceilf ((t0 + 350.f - limT) * 0.5f));
        int nhi = min(NT-1,   (int)floorf((t0 + 350.f + limT) * 0.5f));
        int ncnt = nhi - nlo;
        if (ncnt < 0 || mhi < mlo) continue;

        float hc = 0.5f * c, hs = 0.5f * s;
        float tn0 = -350.f + 2.f * (float)nlo;

        for (int m = mlo; m <= mhi; m++) {
            float rm = d_RV[m];
            float Kx = __fmaf_rn(rm, -hs, cx);
            float Ky = __fmaf_rn(rm,  hc, cy0);
            float W0 = 0.f, W1 = 0.f;
            if (interior) {
                float tn = tn0;
                for (int n = 0; n <= ncnt; n++, tn += 2.f) {
                    float dx = __fmaf_rn(tn, hc, Kx);
                    float dy = __fmaf_rn(tn, hs, Ky);
                    float wx  = fmaxf(1.f - fabsf(dx), 0.f);
                    float wy0 = fmaxf(1.f - fabsf(dy), 0.f);
                    float wy1 = fmaxf(1.f - fabsf(dy - 1.f), 0.f);
                    W0 = __fmaf_rn(wx, wy0, W0);
                    W1 = __fmaf_rn(wx, wy1, W1);
                }
            } else {
                float tn = tn0;
                for (int n = 0; n <= ncnt; n++, tn += 2.f) {
                    float dx = __fmaf_rn(tn, hc, Kx);
                    float dy = __fmaf_rn(tn, hs, Ky);
                    if (dx < vxl || dx > vxh || dy < vyl || dy > vyh) continue;
                    float wx  = fmaxf(1.f - fabsf(dx), 0.f);
                    float wy0 = fmaxf(1.f - fabsf(dy), 0.f);
                    float wy1 = fmaxf(1.f - fabsf(dy - 1.f), 0.f);
                    W0 = __fmaf_rn(wx, wy0, W0);
                    W1 = __fmaf_rn(wx, wy1, W1);
                }
            }
            if (W0 != 0.f || W1 != 0.f) {
                const ulonglong2* zp = (const ulonglong2*)(zr + (phi*NRAD + m)*N0);
                ulonglong2 p0 = zp[0], p1 = zp[1], p2 = zp[2], p3 = zp[3];
                unsigned long long W0p = f2_pack(W0, W0);
                unsigned long long W1p = f2_pack(W1, W1);
                f2_fma(a0[0], W0p, p0.x); f2_fma(a1[0], W1p, p0.x);
                f2_fma(a0[1], W0p, p0.y); f2_fma(a1[1], W1p, p0.y);
                f2_fma(a0[2], W0p, p1.x); f2_fma(a1[2], W1p, p1.x);
                f2_fma(a0[3], W0p, p1.y); f2_fma(a1[3], W1p, p1.y);
                f2_fma(a0[4], W0p, p2.x); f2_fma(a1[4], W1p, p2.x);
                f2_fma(a0[5], W0p, p2.y); f2_fma(a1[5], W1p, p2.y);
                f2_fma(a0[6], W0p, p3.x); f2_fma(a1[6], W1p, p3.x);
                f2_fma(a0[7], W0p, p3.y); f2_fma(a1[7], W1p, p3.y);
            }
        }
    }
    float* dst = bp + ch * NVOX;
    int pix = i * N2 + j0;
    #pragma unroll
    for (int k = 0; k < 8; k++) {
        float2 u0 = f2_unpack(a0[k]);   // pixel0: z = 2k, 2k+1
        float2 u1 = f2_unpack(a1[k]);   // pixel1
        float2 s0 = make_float2(u0.x * 2.f, u1.x * 2.f);
        float2 s1 = make_float2(u0.y * 2.f, u1.y * 2.f);
        *((float2*)(dst + (2*k  )*NPIX + pix)) = s0;
        *((float2*)(dst + (2*k+1)*NPIX + pix)) = s1;
    }
}

// ---------------- combine partial backprojections (float4) ------------------
__global__ void k_combine(const float* __restrict__ bp, float* __restrict__ g)
{
    int t = blockIdx.x * blockDim.x + threadIdx.x;
    if (t >= NVOX/4) return;
    float4 s = make_float4(0.f, 0.f, 0.f, 0.f);
    #pragma unroll
    for (int c = 0; c < NCH; c++) {
        float4 v = ((const float4*)bp)[c*(NVOX/4) + t];
        s.x += v.x; s.y += v.y; s.z += v.z; s.w += v.w;
    }
    ((float4*)g)[t] = s;
}

// ---------------- adjoint gauss: fused j+z smooth ----------------------------
__global__ void k_smooth_jz(const float* __restrict__ in, float* __restrict__ out)
{
    __shared__ float tj[N0][N2 + 1];
    int i = blockIdx.x;
    for (int t = threadIdx.x; t < N0*N2; t += blockDim.x) {
        int j = t % N2;
        int z = t / N2;
        const float* base = in + z*NPIX + i*N2;
        float s = 0.f;
        if (j >= GR && j < N2-GR) {
            #pragma unroll
            for (int d = -GR; d <= GR; d++)
                s += d_GW[d+GR] * base[j+d];
        } else {
            #pragma unroll
            for (int d = -GR; d <= GR; d++)
                s += d_GW[d+GR] * base[refl(j+d, N2)];
        }
        tj[z][j] = s;
    }
    __syncthreads();
    for (int t = threadIdx.x; t < N0*N2; t += blockDim.x) {
        int j = t % N2;
        int z = t / N2;
        float s = 0.f;
        #pragma unroll
        for (int d = -GR; d <= GR; d++) {
            int m = z + d;
            if (m < 0)   m = -1 - m;
            if (m >= N0) m = 2*N0 - 1 - m;
            s += d_GW[d+GR] * tj[m][j];
        }
        out[z*NPIX + i*N2 + j] = s;
    }
}

// ---------------- adjoint i-smooth + MLEM update -----------------------------
__global__ void k_smooth_i_final(const float* __restrict__ gin,
                                 const float* __restrict__ x,
                                 const float* __restrict__ sens,
                                 float* __restrict__ out)
{
    int t = blockIdx.x * blockDim.x + threadIdx.x;
    if (t >= NVOX) return;
    int j = t % N2;
    int i = (t / N2) % N1;
    int z = t / NPIX;
    const float* base = gin + z*NPIX + j;
    float s = 0.f;
    if (i >= GR && i < N1-GR) {
        #pragma unroll
        for (int d = -GR; d <= GR; d++)
            s += d_GW[d+GR] * base[(i+d) * N2];
    } else {
        #pragma unroll
        for (int d = -GR; d <= GR; d++)
            s += d_GW[d+GR] * base[refl(i+d, N1) * N2];
    }
    out[t] = x[t] * s / sens[t];
}

// ---------------- launch ----------------------------------------------------
extern "C" void kernel_launch(void* const* d_in, const int* in_sizes, int n_in,
                              void* d_out, int out_size)
{
    const float* x      = (const float*)d_in[0];
    const float* data   = (const float*)d_in[1];
    const float* contam = (const float*)d_in[2];
    const float* mult   = (const float*)d_in[3];
    const float* sens   = (const float*)d_in[4];
    float* out = (float*)d_out;

    float *buf0, *buf1, *st2, *zr, *bp;
    cudaGetSymbolAddress((void**)&buf0, d_buf0);
    cudaGetSymbolAddress((void**)&buf1, d_buf1);
    cudaGetSymbolAddress((void**)&st2,  d_st2);
    cudaGetSymbolAddress((void**)&zr,   d_zr);
    cudaGetSymbolAddress((void**)&bp,   d_bp);

    k_init<<<1, 256>>>();

    // forward: fused gauss3 + paired transposed image
    k_gauss3t2<<<N1, 512>>>(x, st2);

    // project + exp + ratio (fused, 8 lanes/ray)
    k_project<<<(NSLOT*8 + 255)/256, 256>>>(st2, data, contam, mult, zr);

    // adjoint: backproject (pixel pairs, phi-chunked)  [4th launch -> ncu]
    k_backproject<<<(NCH*NPAIR + 255)/256, 256>>>(zr, bp);
    k_combine<<<(NVOX/4 + 255)/256, 256>>>(bp, buf0);
    k_smooth_jz<<<N1, 512>>>(buf0, buf1);
    k_smooth_i_final<<<(NVOX + 255)/256, 256>>>(buf1, x, sens, out);
}

// round 9
// speedup vs baseline: 1.1743x; 1.1743x over previous
#include <cuda_runtime.h>

#define N0 16
#define N1 200
#define N2 200
#define NPIX (N1*N2)          // 40000
#define NVOX (N0*NPIX)        // 640000
#define NPHI 190
#define NRAD 223
#define NT 351
#define GR 4                  // gaussian radius
#define NSLOT (NPHI*NRAD)     // 42370
#define NCH 8                 // phi chunks for backprojection
#define CHW 24                // ceil(190/8)

// ---------------- scratch (device globals; no allocation allowed) ----------
__device__ __align__(16) float d_GW[2*GR+1];
__device__ float d_COS[NPHI];
__device__ float d_SIN[NPHI];
__device__ float d_RV[NRAD];
__device__ __align__(16) float d_buf1[NVOX];
__device__ __align__(16) float d_st2[2*NVOX + 2*N0*N2];  // paired img + pad i-row
__device__ __align__(16) float d_zr[NSLOT*N0];           // mult*data/exp, [sidx][z]
__device__ __align__(16) float d_bp[NCH*NVOX];           // backprojection partials

// ---------------- packed f32x2 helpers (Blackwell) --------------------------
__device__ __forceinline__ unsigned long long f2_pack(float a, float b)
{
    unsigned long long r;
    asm("mov.b64 %0, {%1,%2};" : "=l"(r) : "f"(a), "f"(b));
    return r;
}
__device__ __forceinline__ void f2_fma(unsigned long long& d,
                                       unsigned long long a, unsigned long long b)
{
    asm("fma.rn.f32x2 %0, %1, %2, %0;" : "+l"(d) : "l"(a), "l"(b));
}
__device__ __forceinline__ unsigned long long f2_add(unsigned long long a,
                                                     unsigned long long b)
{
    unsigned long long r;
    asm("add.rn.f32x2 %0, %1, %2;" : "=l"(r) : "l"(a), "l"(b));
    return r;
}
__device__ __forceinline__ float2 f2_unpack(unsigned long long v)
{
    float2 r;
    asm("mov.b64 {%0,%1}, %2;" : "=f"(r.x), "=f"(r.y) : "l"(v));
    return r;
}

// ---------------- constant tables (match numpy float64 -> float32) ---------
__global__ void k_init()
{
    int t = blockIdx.x * blockDim.x + threadIdx.x;
    if (t == 0) {
        const double sigma = 4.5 / (2.35 * 2.0);
        double g[2*GR+1];
        double sum = 0.0;
        for (int k = 0; k <= 2*GR; k++) {
            double d = (double)(k - GR) / sigma;
            g[k] = exp(-0.5 * d * d);
            sum += g[k];
        }
        for (int k = 0; k <= 2*GR; k++) d_GW[k] = (float)(g[k] / sum);
    }
    const double PI = 3.14159265358979323846;
    for (int i = t; i < NPHI; i += blockDim.x * gridDim.x) {
        float phi = (float)((double)i * (PI / 190.0));   // linspace f64 -> f32
        d_COS[i] = (float)cos((double)phi);
        d_SIN[i] = (float)sin((double)phi);
    }
    for (int i = t; i < NRAD; i += blockDim.x * gridDim.x) {
        d_RV[i] = (float)(-200.0 + (double)i * (400.0 / 222.0));
    }
}

__device__ __forceinline__ int refl(int m, int n)
{
    if (m < 0)  m = -1 - m;
    if (m >= n) m = 2*n - 1 - m;
    return m;
}

// ---------------- fused forward gauss3 + paired z-transpose -----------------
__global__ void k_gauss3t2(const float* __restrict__ in, float* __restrict__ out2)
{
    __shared__ float ta[N0][N2 + 1];
    __shared__ float tb[N0][N2 + 1];
    int i = blockIdx.x;
    int ridx[2*GR+1];
    #pragma unroll
    for (int d = -GR; d <= GR; d++) ridx[d+GR] = refl(i + d, N1);
    // phase 1: i-smooth
    for (int t = threadIdx.x; t < N0*N2; t += blockDim.x) {
        int j = t % N2;
        int z = t / N2;
        const float* base = in + z*NPIX + j;
        float s = 0.f;
        #pragma unroll
        for (int d = 0; d < 2*GR+1; d++)
            s += d_GW[d] * base[ridx[d]*N2];
        ta[z][j] = s;
    }
    __syncthreads();
    // phase 2: j-smooth (ta -> tb)
    for (int t = threadIdx.x; t < N0*N2; t += blockDim.x) {
        int j = t % N2;
        int z = t / N2;
        float s = 0.f;
        if (j >= GR && j < N2-GR) {
            #pragma unroll
            for (int d = -GR; d <= GR; d++)
                s += d_GW[d+GR] * ta[z][j+d];
        } else {
            #pragma unroll
            for (int d = -GR; d <= GR; d++)
                s += d_GW[d+GR] * ta[z][refl(j+d, N2)];
        }
        tb[z][j] = s;
    }
    __syncthreads();
    // phase 3: z-smooth (tb -> ta)
    for (int t = threadIdx.x; t < N0*N2; t += blockDim.x) {
        int j = t % N2;
        int z = t / N2;
        float s = 0.f;
        #pragma unroll
        for (int d = -GR; d <= GR; d++) {
            int m = z + d;
            if (m < 0)   m = -1 - m;
            if (m >= N0) m = 2*N0 - 1 - m;
            s += d_GW[d+GR] * tb[m][j];
        }
        ta[z][j] = s;
    }
    __syncthreads();
    // phase 4: paired-z writes
    for (int t = threadIdx.x; t < N0*N2; t += blockDim.x) {
        int z = t & (N0-1);
        int j = t >> 4;
        int j1 = min(j + 1, N2 - 1);
        float v0 = ta[z][j];
        float v1 = ta[z][j1];
        unsigned base = ((unsigned)(i*N2 + j)) << 5;
        out2[base + z]      = v0;
        out2[base + N0 + z] = v1;
        if (i == N1-1) {   // pad row i = N1 duplicates i = N1-1
            unsigned pbase = ((unsigned)(N1*N2 + j)) << 5;
            out2[pbase + z]      = v0;
            out2[pbase + N0 + z] = v1;
        }
    }
}

// ---------------- forward projection + ratio (fused) ------------------------
// 8 lanes per ray, same sample n; lanes load one 128B pair-block per corner.
// The valid sample set is a CONTIGUOUS n-interval (ix, iy linear in n), so we
// trim nlo/nhi with the identical fp formula and run the hot loop checkless.
__global__ void k_project(const float* __restrict__ st2,
                          const float* __restrict__ data,
                          const float* __restrict__ contam,
                          const float* __restrict__ mult,
                          float* __restrict__ zr)
{
    int t = blockIdx.x * blockDim.x + threadIdx.x;
    int lane8 = t & 7;
    int ray   = t >> 3;
    bool live = (ray < NSLOT);
    if (!live) ray = NSLOT - 1;           // clamp: keep all 32 lanes for shfl
    int phi = ray / NRAD;
    int rad = ray - phi * NRAD;
    int zq  = lane8 & 3;
    bool isj1 = lane8 >= 4;
    float wjb = isj1 ? 0.f : 1.f;         // wj = fma(fj, wjs, wjb)
    float wjs = isj1 ? 1.f : -1.f;

    float c = d_COS[phi], s = d_SIN[phi];
    float r = d_RV[rad];
    float rns = r * (-s);
    float rc  = r * c;

    float A = 0.5f * (rns + 199.f) - 175.f * c;
    float B = 0.5f * (rc  + 199.f) - 175.f * s;

    const float EPS = 1e-6f;
    float lo = 0.f, hi = 350.f;
    bool empty = false;
    if (fabsf(c) > EPS) {
        float n0 = (0.f   - A) / c;
        float n1 = (199.f - A) / c;
        lo = fmaxf(lo, fminf(n0, n1)); hi = fminf(hi, fmaxf(n0, n1));
    } else if (A < 0.f || A > 199.f) empty = true;
    if (fabsf(s) > EPS) {
        float n0 = (0.f   - B) / s;
        float n1 = (199.f - B) / s;
        lo = fmaxf(lo, fminf(n0, n1)); hi = fminf(hi, fmaxf(n0, n1));
    } else if (B < 0.f || B > 199.f) empty = true;

    unsigned long long acc01 = 0ull, acc23 = 0ull;
    if (!empty && hi >= lo) {
        int nlo = max(0,    (int)floorf(lo) - 1);
        int nhi = min(NT-1, (int)ceilf (hi) + 1);
        float hc = 0.5f * c, hs = 0.5f * s;
        float Kx = 0.5f * (rns + 199.f);
        float Ky = 0.5f * (rc  + 199.f);

        // trim to the exact valid contiguous interval (same fp formula)
        while (nlo <= nhi) {
            float tn = -350.f + 2.f * (float)nlo;
            float ix = __fmaf_rn(tn, hc, Kx);
            float iy = __fmaf_rn(tn, hs, Ky);
            if (ix >= 0.f && ix <= 199.f && iy >= 0.f && iy <= 199.f) break;
            nlo++;
        }
        while (nhi >= nlo) {
            float tn = -350.f + 2.f * (float)nhi;
            float ix = __fmaf_rn(tn, hc, Kx);
            float iy = __fmaf_rn(tn, hs, Ky);
            if (ix >= 0.f && ix <= 199.f && iy >= 0.f && iy <= 199.f) break;
            nhi--;
        }

        float tn = -350.f + 2.f * (float)nlo;
        for (int n = nlo; n <= nhi; n++, tn += 2.f) {
            float ix = __fmaf_rn(tn, hc, Kx);
            float iy = __fmaf_rn(tn, hs, Ky);
            int i0 = (int)ix;
            int j0 = (int)iy;
            float fi = ix - (float)i0;
            float fj = iy - (float)j0;
            float wj = __fmaf_rn(fj, wjs, wjb);
            unsigned base = ((unsigned)(i0*N2 + j0)) << 5;
            const unsigned iofs = (unsigned)(N2*2*N0);            // pad row
            ulonglong2 q0 = *((const ulonglong2*)(st2 + base) + lane8);
            ulonglong2 q1 = *((const ulonglong2*)(st2 + base + iofs) + lane8);
            float w0 = wj * (1.f - fi);
            float w1 = wj * fi;
            unsigned long long w0p = f2_pack(w0, w0);
            unsigned long long w1p = f2_pack(w1, w1);
            f2_fma(acc01, w0p, q0.x);
            f2_fma(acc01, w1p, q1.x);
            f2_fma(acc23, w0p, q0.y);
            f2_fma(acc23, w1p, q1.y);
        }
    }

    acc01 = f2_add(acc01, __shfl_down_sync(0xffffffffu, acc01, 4));
    acc23 = f2_add(acc23, __shfl_down_sync(0xffffffffu, acc23, 4));

    if (live && !isj1) {
        int sidx = ray;
        float2 u01 = f2_unpack(acc01);
        float2 u23 = f2_unpack(acc23);
        float pr[4] = { u01.x*2.f, u01.y*2.f, u23.x*2.f, u23.y*2.f };
        float4 o;
        float* ov = (float*)&o;
        #pragma unroll
        for (int k = 0; k < 4; k++) {
            int gi = (zq*4 + k) * NSLOT + sidx;
            float mm = mult[gi];
            float e  = __fmaf_rn(mm, pr[k], contam[gi]);
            ov[k] = mm * data[gi] / e;
        }
        ((float4*)zr)[sidx*4 + zq] = o;
    }
}

// ---------------- backprojection (round-7 version: known 144us) -------------
__global__ void k_backproject(const float* __restrict__ zr, float* __restrict__ bp)
{
    int tid = blockIdx.x * blockDim.x + threadIdx.x;
    if (tid >= NCH * NPIX) return;
    int pix = tid % NPIX;
    int ch  = tid / NPIX;
    int i = pix / N2, j = pix % N2;
    float X = -199.f + 2.f * (float)i;
    float Y = -199.f + 2.f * (float)j;

    unsigned long long accp[8];
    #pragma unroll
    for (int k = 0; k < 8; k++) accp[k] = 0ull;

    const float inv_dr = (float)(222.0 / 400.0);
    float cx = 99.5f - (float)i;
    float cy = 99.5f - (float)j;
    float vxl = -(float)i,  vxh = 199.f - (float)i;
    float vyl = -(float)j,  vyh = 199.f - (float)j;
    bool interior = (i >= 1 && i <= N1-2 && j >= 1 && j <= N2-2);

    int plo = ch * CHW;
    int phi_end = min(NPHI, plo + CHW);

    for (int phi = plo; phi < phi_end; phi++) {
        float c = d_COS[phi], s = d_SIN[phi];
        float lim = 2.f * (fabsf(c) + fabsf(s)) + 1e-2f;
        float r0 = -X*s + Y*c;
        float t0 =  X*c + Y*s;
        int mlo = max(0,      (int)ceilf ((r0 + 200.f - lim) * inv_dr));
        int mhi = min(NRAD-1, (int)floorf((r0 + 200.f + lim) * inv_dr));
        int nlo = max(0,      (int)ceilf ((t0 + 350.f - lim) * 0.5f));
        int nhi = min(NT-1,   (int)floorf((t0 + 350.f + lim) * 0.5f));
        int ncnt = nhi - nlo;
        if (ncnt < 0 || mhi < mlo) continue;

        float hc = 0.5f * c, hs = 0.5f * s;
        float tn0 = -350.f + 2.f * (float)nlo;

        for (int m = mlo; m <= mhi; m++) {
            float rm = d_RV[m];
            float Kx = __fmaf_rn(rm, -hs, cx);
            float Ky = __fmaf_rn(rm,  hc, cy);
            float W = 0.f;
            if (interior) {
                float tn = tn0;
                for (int n = 0; n <= ncnt; n++, tn += 2.f) {
                    float dx = __fmaf_rn(tn, hc, Kx);
                    float dy = __fmaf_rn(tn, hs, Ky);
                    float wx = fmaxf(1.f - fabsf(dx), 0.f);
                    float wy = fmaxf(1.f - fabsf(dy), 0.f);
                    W = __fmaf_rn(wx, wy, W);
                }
            } else {
                float tn = tn0;
                for (int n = 0; n <= ncnt; n++, tn += 2.f) {
                    float dx = __fmaf_rn(tn, hc, Kx);
                    float dy = __fmaf_rn(tn, hs, Ky);
                    if (dx < vxl || dx > vxh || dy < vyl || dy > vyh) continue;
                    float wx = fmaxf(1.f - fabsf(dx), 0.f);
                    float wy = fmaxf(1.f - fabsf(dy), 0.f);
                    W = __fmaf_rn(wx, wy, W);
                }
            }
            if (W != 0.f) {
                const ulonglong2* zp = (const ulonglong2*)(zr + (phi*NRAD + m)*N0);
                ulonglong2 p0 = zp[0], p1 = zp[1], p2 = zp[2], p3 = zp[3];
                unsigned long long Wp = f2_pack(W, W);
                f2_fma(accp[0], Wp, p0.x);
                f2_fma(accp[1], Wp, p0.y);
                f2_fma(accp[2], Wp, p1.x);
                f2_fma(accp[3], Wp, p1.y);
                f2_fma(accp[4], Wp, p2.x);
                f2_fma(accp[5], Wp, p2.y);
                f2_fma(accp[6], Wp, p3.x);
                f2_fma(accp[7], Wp, p3.y);
            }
        }
    }
    float* dst = bp + ch * NVOX;
    #pragma unroll
    for (int k = 0; k < 8; k++) {
        float2 u = f2_unpack(accp[k]);
        dst[(2*k  )*NPIX + pix] = u.x * 2.f;   // * STEP
        dst[(2*k+1)*NPIX + pix] = u.y * 2.f;
    }
}

// ---------------- adjoint gauss: fused combine + j-smooth + z-smooth --------
__global__ void k_smooth_jz(const float* __restrict__ bp, float* __restrict__ out)
{
    __shared__ float ta[N0][N2 + 1];
    __shared__ float tj[N0][N2 + 1];
    int i = blockIdx.x;
    // phase 0: combine NCH backprojection partials
    for (int t = threadIdx.x; t < N0*N2; t += blockDim.x) {
        int j = t % N2;
        int z = t / N2;
        const float* base = bp + z*NPIX + i*N2 + j;
        float s = 0.f;
        #pragma unroll
        for (int ch = 0; ch < NCH; ch++)
            s += base[ch*NVOX];
        ta[z][j] = s;
    }
    __syncthreads();
    // phase 1: j-smooth (ta -> tj)
    for (int t = threadIdx.x; t < N0*N2; t += blockDim.x) {
        int j = t % N2;
        int z = t / N2;
        float s = 0.f;
        if (j >= GR && j < N2-GR) {
            #pragma unroll
            for (int d = -GR; d <= GR; d++)
                s += d_GW[d+GR] * ta[z][j+d];
        } else {
            #pragma unroll
            for (int d = -GR; d <= GR; d++)
                s += d_GW[d+GR] * ta[z][refl(j+d, N2)];
        }
        tj[z][j] = s;
    }
    __syncthreads();
    // phase 2: z-smooth -> global
    for (int t = threadIdx.x; t < N0*N2; t += blockDim.x) {
        int j = t % N2;
        int z = t / N2;
        float s = 0.f;
        #pragma unroll
        for (int d = -GR; d <= GR; d++) {
            int m = z + d;
            if (m < 0)   m = -1 - m;
            if (m >= N0) m = 2*N0 - 1 - m;
            s += d_GW[d+GR] * tj[m][j];
        }
        out[z*NPIX + i*N2 + j] = s;
    }
}

// ---------------- adjoint i-smooth + MLEM update -----------------------------
__global__ void k_smooth_i_final(const float* __restrict__ gin,
                                 const float* __restrict__ x,
                                 const float* __restrict__ sens,
                                 float* __restrict__ out)
{
    int t = blockIdx.x * blockDim.x + threadIdx.x;
    if (t >= NVOX) return;
    int j = t % N2;
    int i = (t / N2) % N1;
    int z = t / NPIX;
    const float* base = gin + z*NPIX + j;
    float s = 0.f;
    if (i >= GR && i < N1-GR) {
        #pragma unroll
        for (int d = -GR; d <= GR; d++)
            s += d_GW[d+GR] * base[(i+d) * N2];
    } else {
        #pragma unroll
        for (int d = -GR; d <= GR; d++)
            s += d_GW[d+GR] * base[refl(i+d, N1) * N2];
    }
    out[t] = x[t] * s / sens[t];
}

// ---------------- launch ----------------------------------------------------
extern "C" void kernel_launch(void* const* d_in, const int* in_sizes, int n_in,
                              void* d_out, int out_size)
{
    const float* x      = (const float*)d_in[0];
    const float* data   = (const float*)d_in[1];
    const float* contam = (const float*)d_in[2];
    const float* mult   = (const float*)d_in[3];
    const float* sens   = (const float*)d_in[4];
    float* out = (float*)d_out;

    float *buf1, *st2, *zr, *bp;
    cudaGetSymbolAddress((void**)&buf1, d_buf1);
    cudaGetSymbolAddress((void**)&st2,  d_st2);
    cudaGetSymbolAddress((void**)&zr,   d_zr);
    cudaGetSymbolAddress((void**)&bp,   d_bp);

    k_init<<<1, 256>>>();

    // forward: fused gauss3 + paired transposed image
    k_gauss3t2<<<N1, 512>>>(x, st2);

    // project + exp + ratio (fused, 8 lanes/ray, checkless hot loop)
    k_project<<<(NSLOT*8 + 255)/256, 256>>>(st2, data, contam, mult, zr);

    // adjoint: backproject (round-7), fused combine+j+z smooth, i-smooth+MLEM
    k_backproject<<<(NCH*NPIX + 255)/256, 256>>>(zr, bp);
    k_smooth_jz<<<N1, 512>>>(bp, buf1);
    k_smooth_i_final<<<(NVOX + 255)/256, 256>>>(buf1, x, sens, out);
}

// round 10
// speedup vs baseline: 1.2026x; 1.0241x over previous
#include <cuda_runtime.h>

#define N0 16
#define N1 200
#define N2 200
#define NPIX (N1*N2)          // 40000
#define NVOX (N0*NPIX)        // 640000
#define NPHI 190
#define NRAD 223
#define NT 351
#define GR 4                  // gaussian radius
#define NSLOT (NPHI*NRAD)     // 42370
#define NCH 8                 // phi chunks for backprojection
#define CHW 24                // ceil(190/8)

// ---------------- scratch (device globals; no allocation allowed) ----------
__device__ __align__(16) float d_GW[2*GR+1];
__device__ float d_COS[NPHI];
__device__ float d_SIN[NPHI];
__device__ float d_RV[NRAD];
__device__ __align__(16) float d_buf1[NVOX];
__device__ __align__(16) float d_st2[2*NVOX + 2*N0*N2];  // paired img + pad i-row
__device__ __align__(16) float d_zr[NSLOT*N0];           // mult*data/exp, [sidx][z]
__device__ __align__(16) float d_bp[NCH*NVOX];           // backprojection partials

// ---------------- packed f32x2 helpers (Blackwell) --------------------------
__device__ __forceinline__ unsigned long long f2_pack(float a, float b)
{
    unsigned long long r;
    asm("mov.b64 %0, {%1,%2};" : "=l"(r) : "f"(a), "f"(b));
    return r;
}
__device__ __forceinline__ void f2_fma(unsigned long long& d,
                                       unsigned long long a, unsigned long long b)
{
    asm("fma.rn.f32x2 %0, %1, %2, %0;" : "+l"(d) : "l"(a), "l"(b));
}
__device__ __forceinline__ unsigned long long f2_add(unsigned long long a,
                                                     unsigned long long b)
{
    unsigned long long r;
    asm("add.rn.f32x2 %0, %1, %2;" : "=l"(r) : "l"(a), "l"(b));
    return r;
}
__device__ __forceinline__ float2 f2_unpack(unsigned long long v)
{
    float2 r;
    asm("mov.b64 {%0,%1}, %2;" : "=f"(r.x), "=f"(r.y) : "l"(v));
    return r;
}

// ---------------- constant tables (match numpy float64 -> float32) ---------
__global__ void k_init()
{
    int t = blockIdx.x * blockDim.x + threadIdx.x;
    if (t == 0) {
        const double sigma = 4.5 / (2.35 * 2.0);
        double g[2*GR+1];
        double sum = 0.0;
        for (int k = 0; k <= 2*GR; k++) {
            double d = (double)(k - GR) / sigma;
            g[k] = exp(-0.5 * d * d);
            sum += g[k];
        }
        for (int k = 0; k <= 2*GR; k++) d_GW[k] = (float)(g[k] / sum);
    }
    const double PI = 3.14159265358979323846;
    for (int i = t; i < NPHI; i += blockDim.x * gridDim.x) {
        float phi = (float)((double)i * (PI / 190.0));   // linspace f64 -> f32
        d_COS[i] = (float)cos((double)phi);
        d_SIN[i] = (float)sin((double)phi);
    }
    for (int i = t; i < NRAD; i += blockDim.x * gridDim.x) {
        d_RV[i] = (float)(-200.0 + (double)i * (400.0 / 222.0));
    }
}

__device__ __forceinline__ int refl(int m, int n)
{
    if (m < 0)  m = -1 - m;
    if (m >= n) m = 2*n - 1 - m;
    return m;
}

// ---------------- fused forward gauss3 + paired z-transpose -----------------
__global__ void k_gauss3t2(const float* __restrict__ in, float* __restrict__ out2)
{
    __shared__ float ta[N0][N2 + 1];
    __shared__ float tb[N0][N2 + 1];
    int i = blockIdx.x;
    int ridx[2*GR+1];
    #pragma unroll
    for (int d = -GR; d <= GR; d++) ridx[d+GR] = refl(i + d, N1);
    // phase 1: i-smooth
    for (int t = threadIdx.x; t < N0*N2; t += blockDim.x) {
        int j = t % N2;
        int z = t / N2;
        const float* base = in + z*NPIX + j;
        float s = 0.f;
        #pragma unroll
        for (int d = 0; d < 2*GR+1; d++)
            s += d_GW[d] * base[ridx[d]*N2];
        ta[z][j] = s;
    }
    __syncthreads();
    // phase 2: j-smooth (ta -> tb)
    for (int t = threadIdx.x; t < N0*N2; t += blockDim.x) {
        int j = t % N2;
        int z = t / N2;
        float s = 0.f;
        if (j >= GR && j < N2-GR) {
            #pragma unroll
            for (int d = -GR; d <= GR; d++)
                s += d_GW[d+GR] * ta[z][j+d];
        } else {
            #pragma unroll
            for (int d = -GR; d <= GR; d++)
                s += d_GW[d+GR] * ta[z][refl(j+d, N2)];
        }
        tb[z][j] = s;
    }
    __syncthreads();
    // phase 3: z-smooth (tb -> ta)
    for (int t = threadIdx.x; t < N0*N2; t += blockDim.x) {
        int j = t % N2;
        int z = t / N2;
        float s = 0.f;
        #pragma unroll
        for (int d = -GR; d <= GR; d++) {
            int m = z + d;
            if (m < 0)   m = -1 - m;
            if (m >= N0) m = 2*N0 - 1 - m;
            s += d_GW[d+GR] * tb[m][j];
        }
        ta[z][j] = s;
    }
    __syncthreads();
    // phase 4: paired-z writes
    for (int t = threadIdx.x; t < N0*N2; t += blockDim.x) {
        int z = t & (N0-1);
        int j = t >> 4;
        int j1 = min(j + 1, N2 - 1);
        float v0 = ta[z][j];
        float v1 = ta[z][j1];
        unsigned base = ((unsigned)(i*N2 + j)) << 5;
        out2[base + z]      = v0;
        out2[base + N0 + z] = v1;
        if (i == N1-1) {   // pad row i = N1 duplicates i = N1-1
            unsigned pbase = ((unsigned)(N1*N2 + j)) << 5;
            out2[pbase + z]      = v0;
            out2[pbase + N0 + z] = v1;
        }
    }
}

// ---------------- forward projection + ratio (fused) ------------------------
// 8 lanes per ray, same sample n; lanes load one 128B pair-block per corner.
// The valid sample set is a CONTIGUOUS n-interval (ix, iy linear in n), so we
// trim nlo/nhi with the identical fp formula and run the hot loop checkless.
__global__ void k_project(const float* __restrict__ st2,
                          const float* __restrict__ data,
                          const float* __restrict__ contam,
                          const float* __restrict__ mult,
                          float* __restrict__ zr)
{
    int t = blockIdx.x * blockDim.x + threadIdx.x;
    int lane8 = t & 7;
    int ray   = t >> 3;
    bool live = (ray < NSLOT);
    if (!live) ray = NSLOT - 1;           // clamp: keep all 32 lanes for shfl
    int phi = ray / NRAD;
    int rad = ray - phi * NRAD;
    int zq  = lane8 & 3;
    bool isj1 = lane8 >= 4;
    float wjb = isj1 ? 0.f : 1.f;         // wj = fma(fj, wjs, wjb)
    float wjs = isj1 ? 1.f : -1.f;

    float c = d_COS[phi], s = d_SIN[phi];
    float r = d_RV[rad];
    float rns = r * (-s);
    float rc  = r * c;

    float A = 0.5f * (rns + 199.f) - 175.f * c;
    float B = 0.5f * (rc  + 199.f) - 175.f * s;

    const float EPS = 1e-6f;
    float lo = 0.f, hi = 350.f;
    bool empty = false;
    if (fabsf(c) > EPS) {
        float n0 = (0.f   - A) / c;
        float n1 = (199.f - A) / c;
        lo = fmaxf(lo, fminf(n0, n1)); hi = fminf(hi, fmaxf(n0, n1));
    } else if (A < 0.f || A > 199.f) empty = true;
    if (fabsf(s) > EPS) {
        float n0 = (0.f   - B) / s;
        float n1 = (199.f - B) / s;
        lo = fmaxf(lo, fminf(n0, n1)); hi = fminf(hi, fmaxf(n0, n1));
    } else if (B < 0.f || B > 199.f) empty = true;

    unsigned long long acc01 = 0ull, acc23 = 0ull;
    if (!empty && hi >= lo) {
        int nlo = max(0,    (int)floorf(lo) - 1);
        int nhi = min(NT-1, (int)ceilf (hi) + 1);
        float hc = 0.5f * c, hs = 0.5f * s;
        float Kx = 0.5f * (rns + 199.f);
        float Ky = 0.5f * (rc  + 199.f);

        // trim to the exact valid contiguous interval (same fp formula)
        while (nlo <= nhi) {
            float tn = -350.f + 2.f * (float)nlo;
            float ix = __fmaf_rn(tn, hc, Kx);
            float iy = __fmaf_rn(tn, hs, Ky);
            if (ix >= 0.f && ix <= 199.f && iy >= 0.f && iy <= 199.f) break;
            nlo++;
        }
        while (nhi >= nlo) {
            float tn = -350.f + 2.f * (float)nhi;
            float ix = __fmaf_rn(tn, hc, Kx);
            float iy = __fmaf_rn(tn, hs, Ky);
            if (ix >= 0.f && ix <= 199.f && iy >= 0.f && iy <= 199.f) break;
            nhi--;
        }

        float tn = -350.f + 2.f * (float)nlo;
        for (int n = nlo; n <= nhi; n++, tn += 2.f) {
            float ix = __fmaf_rn(tn, hc, Kx);
            float iy = __fmaf_rn(tn, hs, Ky);
            int i0 = (int)ix;
            int j0 = (int)iy;
            float fi = ix - (float)i0;
            float fj = iy - (float)j0;
            float wj = __fmaf_rn(fj, wjs, wjb);
            unsigned base = ((unsigned)(i0*N2 + j0)) << 5;
            const unsigned iofs = (unsigned)(N2*2*N0);            // pad row
            ulonglong2 q0 = *((const ulonglong2*)(st2 + base) + lane8);
            ulonglong2 q1 = *((const ulonglong2*)(st2 + base + iofs) + lane8);
            float w0 = wj * (1.f - fi);
            float w1 = wj * fi;
            unsigned long long w0p = f2_pack(w0, w0);
            unsigned long long w1p = f2_pack(w1, w1);
            f2_fma(acc01, w0p, q0.x);
            f2_fma(acc01, w1p, q1.x);
            f2_fma(acc23, w0p, q0.y);
            f2_fma(acc23, w1p, q1.y);
        }
    }

    acc01 = f2_add(acc01, __shfl_down_sync(0xffffffffu, acc01, 4));
    acc23 = f2_add(acc23, __shfl_down_sync(0xffffffffu, acc23, 4));

    if (live && !isj1) {
        int sidx = ray;
        float2 u01 = f2_unpack(acc01);
        float2 u23 = f2_unpack(acc23);
        float pr[4] = { u01.x*2.f, u01.y*2.f, u23.x*2.f, u23.y*2.f };
        float4 o;
        float* ov = (float*)&o;
        #pragma unroll
        for (int k = 0; k < 4; k++) {
            int gi = (zq*4 + k) * NSLOT + sidx;
            float mm = mult[gi];
            float e  = __fmaf_rn(mm, pr[k], contam[gi]);
            ov[k] = mm * data[gi] / e;
        }
        ((float4*)zr)[sidx*4 + zq] = o;
    }
}

// ---------------- backprojection (tiled-warp gather) -------------------------
// one thread = (pixel, phi-chunk); warp covers an 8j x 4i pixel tile so the
// zr rows touched per warp-LDG span ~(8.9|c|+4.4|s|) rad bins instead of ~35|c|
// -> ~3x fewer L1 line-wavefronts per load. Loop body identical to round 7.
__global__ void k_backproject(const float* __restrict__ zr, float* __restrict__ bp)
{
    int tid = blockIdx.x * blockDim.x + threadIdx.x;
    if (tid >= NCH * NPIX) return;
    int ch = tid / NPIX;
    int u  = tid % NPIX;                  // NPIX % 32 == 0: warps stay in-chunk
    int lane = u & 31;
    int wu   = u >> 5;                    // 0..1249
    int ti = wu / (N2/8);                 // 0..49  (i tile)
    int tj = wu % (N2/8);                 // 0..24  (j tile)
    int i = ti*4 + (lane >> 3);
    int j = tj*8 + (lane & 7);
    int pix = i * N2 + j;

    float X = -199.f + 2.f * (float)i;
    float Y = -199.f + 2.f * (float)j;

    unsigned long long accp[8];
    #pragma unroll
    for (int k = 0; k < 8; k++) accp[k] = 0ull;

    const float inv_dr = (float)(222.0 / 400.0);
    float cx = 99.5f - (float)i;
    float cy = 99.5f - (float)j;
    float vxl = -(float)i,  vxh = 199.f - (float)i;
    float vyl = -(float)j,  vyh = 199.f - (float)j;
    bool interior = (i >= 1 && i <= N1-2 && j >= 1 && j <= N2-2);

    int plo = ch * CHW;
    int phi_end = min(NPHI, plo + CHW);

    for (int phi = plo; phi < phi_end; phi++) {
        float c = d_COS[phi], s = d_SIN[phi];
        float lim = 2.f * (fabsf(c) + fabsf(s)) + 1e-2f;
        float r0 = -X*s + Y*c;
        float t0 =  X*c + Y*s;
        int mlo = max(0,      (int)ceilf ((r0 + 200.f - lim) * inv_dr));
        int mhi = min(NRAD-1, (int)floorf((r0 + 200.f + lim) * inv_dr));
        int nlo = max(0,      (int)ceilf ((t0 + 350.f - lim) * 0.5f));
        int nhi = min(NT-1,   (int)floorf((t0 + 350.f + lim) * 0.5f));
        int ncnt = nhi - nlo;
        if (ncnt < 0 || mhi < mlo) continue;

        float hc = 0.5f * c, hs = 0.5f * s;
        float tn0 = -350.f + 2.f * (float)nlo;

        for (int m = mlo; m <= mhi; m++) {
            float rm = d_RV[m];
            float Kx = __fmaf_rn(rm, -hs, cx);
            float Ky = __fmaf_rn(rm,  hc, cy);
            float W = 0.f;
            if (interior) {
                float tn = tn0;
                for (int n = 0; n <= ncnt; n++, tn += 2.f) {
                    float dx = __fmaf_rn(tn, hc, Kx);
                    float dy = __fmaf_rn(tn, hs, Ky);
                    float wx = fmaxf(1.f - fabsf(dx), 0.f);
                    float wy = fmaxf(1.f - fabsf(dy), 0.f);
                    W = __fmaf_rn(wx, wy, W);
                }
            } else {
                float tn = tn0;
                for (int n = 0; n <= ncnt; n++, tn += 2.f) {
                    float dx = __fmaf_rn(tn, hc, Kx);
                    float dy = __fmaf_rn(tn, hs, Ky);
                    if (dx < vxl || dx > vxh || dy < vyl || dy > vyh) continue;
                    float wx = fmaxf(1.f - fabsf(dx), 0.f);
                    float wy = fmaxf(1.f - fabsf(dy), 0.f);
                    W = __fmaf_rn(wx, wy, W);
                }
            }
            if (W != 0.f) {
                const ulonglong2* zp = (const ulonglong2*)(zr + (phi*NRAD + m)*N0);
                ulonglong2 p0 = zp[0], p1 = zp[1], p2 = zp[2], p3 = zp[3];
                unsigned long long Wp = f2_pack(W, W);
                f2_fma(accp[0], Wp, p0.x);
                f2_fma(accp[1], Wp, p0.y);
                f2_fma(accp[2], Wp, p1.x);
                f2_fma(accp[3], Wp, p1.y);
                f2_fma(accp[4], Wp, p2.x);
                f2_fma(accp[5], Wp, p2.y);
                f2_fma(accp[6], Wp, p3.x);
                f2_fma(accp[7], Wp, p3.y);
            }
        }
    }
    float* dst = bp + ch * NVOX;
    #pragma unroll
    for (int k = 0; k < 8; k++) {
        float2 u2 = f2_unpack(accp[k]);
        dst[(2*k  )*NPIX + pix] = u2.x * 2.f;   // * STEP
        dst[(2*k+1)*NPIX + pix] = u2.y * 2.f;
    }
}

// ---------------- adjoint gauss: fused combine + j-smooth + z-smooth --------
__global__ void k_smooth_jz(const float* __restrict__ bp, float* __restrict__ out)
{
    __shared__ float ta[N0][N2 + 1];
    __shared__ float tj[N0][N2 + 1];
    int i = blockIdx.x;
    // phase 0: combine NCH backprojection partials
    for (int t = threadIdx.x; t < N0*N2; t += blockDim.x) {
        int j = t % N2;
        int z = t / N2;
        const float* base = bp + z*NPIX + i*N2 + j;
        float s = 0.f;
        #pragma unroll
        for (int ch = 0; ch < NCH; ch++)
            s += base[ch*NVOX];
        ta[z][j] = s;
    }
    __syncthreads();
    // phase 1: j-smooth (ta -> tj)
    for (int t = threadIdx.x; t < N0*N2; t += blockDim.x) {
        int j = t % N2;
        int z = t / N2;
        float s = 0.f;
        if (j >= GR && j < N2-GR) {
            #pragma unroll
            for (int d = -GR; d <= GR; d++)
                s += d_GW[d+GR] * ta[z][j+d];
        } else {
            #pragma unroll
            for (int d = -GR; d <= GR; d++)
                s += d_GW[d+GR] * ta[z][refl(j+d, N2)];
        }
        tj[z][j] = s;
    }
    __syncthreads();
    // phase 2: z-smooth -> global
    for (int t = threadIdx.x; t < N0*N2; t += blockDim.x) {
        int j = t % N2;
        int z = t / N2;
        float s = 0.f;
        #pragma unroll
        for (int d = -GR; d <= GR; d++) {
            int m = z + d;
            if (m < 0)   m = -1 - m;
            if (m >= N0) m = 2*N0 - 1 - m;
            s += d_GW[d+GR] * tj[m][j];
        }
        out[z*NPIX + i*N2 + j] = s;
    }
}

// ---------------- adjoint i-smooth + MLEM update -----------------------------
__global__ void k_smooth_i_final(const float* __restrict__ gin,
                                 const float* __restrict__ x,
                                 const float* __restrict__ sens,
                                 float* __restrict__ out)
{
    int t = blockIdx.x * blockDim.x + threadIdx.x;
    if (t >= NVOX) return;
    int j = t % N2;
    int i = (t / N2) % N1;
    int z = t / NPIX;
    const float* base = gin + z*NPIX + j;
    float s = 0.f;
    if (i >= GR && i < N1-GR) {
        #pragma unroll
        for (int d = -GR; d <= GR; d++)
            s += d_GW[d+GR] * base[(i+d) * N2];
    } else {
        #pragma unroll
        for (int d = -GR; d <= GR; d++)
            s += d_GW[d+GR] * base[refl(i+d, N1) * N2];
    }
    out[t] = x[t] * s / sens[t];
}

// ---------------- launch ----------------------------------------------------
extern "C" void kernel_launch(void* const* d_in, const int* in_sizes, int n_in,
                              void* d_out, int out_size)
{
    const float* x      = (const float*)d_in[0];
    const float* data   = (const float*)d_in[1];
    const float* contam = (const float*)d_in[2];
    const float* mult   = (const float*)d_in[3];
    const float* sens   = (const float*)d_in[4];
    float* out = (float*)d_out;

    float *buf1, *st2, *zr, *bp;
    cudaGetSymbolAddress((void**)&buf1, d_buf1);
    cudaGetSymbolAddress((void**)&st2,  d_st2);
    cudaGetSymbolAddress((void**)&zr,   d_zr);
    cudaGetSymbolAddress((void**)&bp,   d_bp);

    k_init<<<1, 256>>>();

    // forward: fused gauss3 + paired transposed image
    k_gauss3t2<<<N1, 512>>>(x, st2);

    // project + exp + ratio (fused, 8 lanes/ray, checkless hot loop)
    k_project<<<(NSLOT*8 + 255)/256, 256>>>(st2, data, contam, mult, zr);

    // adjoint: backproject (tiled warps), fused combine+j+z smooth, i-smooth+MLEM
    k_backproject<<<(NCH*NPIX + 255)/256, 256>>>(zr, bp);
    k_smooth_jz<<<N1, 512>>>(bp, buf1);
    k_smooth_i_final<<<(NVOX + 255)/256, 256>>>(buf1, x, sens, out);
}